// round 12
// baseline (speedup 1.0000x reference)
#include <cuda_runtime.h>

#define BB 2
#define SS 2048
#define DD 768
#define HH 12
#define DKK 64
#define MM (BB*SS)   // 4096

// ---------------- scratch (static device globals) ---------------------------
__device__ float g_q[MM * DD];
__device__ float g_k[MM * DD];
__device__ float g_v[MM * DD];
__device__ float g_o[MM * DD];
__device__ float g_rz[BB * HH * SS];   // 1 / sum_i exp(s[b,h,j,i])
__device__ float g_w [4 * DD * DD];    // tf32-rounded Wq/Wk/Wv/Wo

// ---------------- helpers ----------------------------------------------------
__device__ __forceinline__ void cpa16(void* s, const void* g) {
    unsigned sa = (unsigned)__cvta_generic_to_shared(s);
    asm volatile("cp.async.ca.shared.global [%0], [%1], 16;\n" :: "r"(sa), "l"(g));
}
__device__ __forceinline__ void cp_commit() { asm volatile("cp.async.commit_group;\n"); }
template<int N> __device__ __forceinline__ void cp_wait() {
    asm volatile("cp.async.wait_group %0;\n" :: "n"(N));
}
__device__ __forceinline__ unsigned f2tf(float f) {
    unsigned u;
    asm("cvt.rna.tf32.f32 %0, %1;" : "=r"(u) : "f"(f));
    return u;
}
__device__ __forceinline__ float rndtf(float f) { return __uint_as_float(f2tf(f)); }

// D += A(16x8) * B(8x8), tf32, f32 accum
__device__ __forceinline__ void mma8(float c[4], const unsigned a[4], const unsigned b[2]) {
    asm volatile(
        "mma.sync.aligned.m16n8k8.row.col.f32.tf32.tf32.f32 "
        "{%0,%1,%2,%3}, {%4,%5,%6,%7}, {%8,%9}, {%0,%1,%2,%3};"
        : "+f"(c[0]), "+f"(c[1]), "+f"(c[2]), "+f"(c[3])
        : "r"(a[0]), "r"(a[1]), "r"(a[2]), "r"(a[3]), "r"(b[0]), "r"(b[1]));
}

// ============================================================================
// Weights tf32 pre-rounding (9.4 MB traffic, one launch)
// ============================================================================
__global__ void round_weights_k(const float* __restrict__ wq,
                                const float* __restrict__ wk,
                                const float* __restrict__ wv,
                                const float* __restrict__ wo,
                                float* __restrict__ dst)
{
    const float* src = (blockIdx.y == 0) ? wq : (blockIdx.y == 1) ? wk
                     : (blockIdx.y == 2) ? wv : wo;
    float* d = dst + (size_t)blockIdx.y * DD * DD;
    int idx = (blockIdx.x * 256 + threadIdx.x) << 2;
    if (idx < DD * DD) {
        float4 x = *(const float4*)(src + idx);
        x.x = rndtf(x.x); x.y = rndtf(x.y); x.z = rndtf(x.z); x.w = rndtf(x.w);
        *(float4*)(d + idx) = x;
    }
}

// ============================================================================
// Projection GEMM body: C = ((A @ W) + bias) * scale
// 64m x 128n tile, BK=32 (24 iters), 256 thr (2x4 warps, warp 32x32).
// W is PRE-ROUNDED. RND_A=1 rounds A fragments (raw inputs); 0 = already tf32.
// Dynamic smem 53248 B -> 3 CTAs/SM.
// ============================================================================
#define PAS(buf,m,k)  As[(buf)*2304 + (m)*36 + (k)]
#define PBS(buf,k,n)  Bs[(buf)*4352 + (k)*136 + (n)]

template<int RND_A>
__device__ __forceinline__
void proj_body(const float* __restrict__ A, const float* __restrict__ W,
               const float* __restrict__ bias, float* __restrict__ C,
               float scale, int rnd_out, float* As, float* Bs)
{
    int t = threadIdx.x, lane = t & 31, w = t >> 5;
    int g = lane >> 2, q = lane & 3;
    int wm = (w & 1) << 5, wn = (w >> 1) << 5;
    int m0 = blockIdx.y << 6, n0 = blockIdx.x << 7;

    {
        #pragma unroll
        for (int ch = 0; ch < 2; ch++) {
            int c = t + (ch << 8);
            int ar = c >> 3, akq = (c & 7) << 2;
            cpa16(&PAS(0, ar, akq), A + (size_t)(m0 + ar) * DD + akq);
        }
        #pragma unroll
        for (int ch = 0; ch < 4; ch++) {
            int c = t + (ch << 8);
            int br = c >> 5, bnq = (c & 31) << 2;
            cpa16(&PBS(0, br, bnq), W + (size_t)br * DD + n0 + bnq);
        }
    }
    cp_commit();

    float acc[2][4][4] = {};

    for (int it = 0; it < 24; it++) {
        int buf = it & 1;
        if (it < 23) {
            int k0 = (it + 1) << 5;
            #pragma unroll
            for (int ch = 0; ch < 2; ch++) {
                int c = t + (ch << 8);
                int ar = c >> 3, akq = (c & 7) << 2;
                cpa16(&PAS(buf ^ 1, ar, akq), A + (size_t)(m0 + ar) * DD + k0 + akq);
            }
            #pragma unroll
            for (int ch = 0; ch < 4; ch++) {
                int c = t + (ch << 8);
                int br = c >> 5, bnq = (c & 31) << 2;
                cpa16(&PBS(buf ^ 1, br, bnq), W + (size_t)(k0 + br) * DD + n0 + bnq);
            }
            cp_commit();
            cp_wait<1>();
        } else {
            cp_wait<0>();
        }
        __syncthreads();

        #pragma unroll
        for (int kk = 0; kk < 32; kk += 8) {
            unsigned a[2][4], b2[4][2];
            #pragma unroll
            for (int mi = 0; mi < 2; mi++) {
                const float* pa = &PAS(buf, wm + (mi << 4) + g, kk + q);
                if (RND_A) {
                    a[mi][0] = f2tf(pa[0]);
                    a[mi][1] = f2tf(pa[8 * 36]);
                    a[mi][2] = f2tf(pa[4]);
                    a[mi][3] = f2tf(pa[8 * 36 + 4]);
                } else {
                    a[mi][0] = __float_as_uint(pa[0]);
                    a[mi][1] = __float_as_uint(pa[8 * 36]);
                    a[mi][2] = __float_as_uint(pa[4]);
                    a[mi][3] = __float_as_uint(pa[8 * 36 + 4]);
                }
            }
            #pragma unroll
            for (int ni = 0; ni < 4; ni++) {
                const float* pb = &PBS(buf, kk + q, wn + (ni << 3) + g);
                b2[ni][0] = __float_as_uint(pb[0]);
                b2[ni][1] = __float_as_uint(pb[4 * 136]);
            }
            #pragma unroll
            for (int mi = 0; mi < 2; mi++)
                #pragma unroll
                for (int ni = 0; ni < 4; ni++) mma8(acc[mi][ni], a[mi], b2[ni]);
        }
        __syncthreads();
    }

    #pragma unroll
    for (int ni = 0; ni < 4; ni++) {
        int col = n0 + wn + (ni << 3) + (q << 1);
        float b0 = bias[col], b1 = bias[col + 1];
        #pragma unroll
        for (int mi = 0; mi < 2; mi++) {
            int row = m0 + wm + (mi << 4) + g;
            float o0 = (acc[mi][ni][0] + b0) * scale;
            float o1 = (acc[mi][ni][1] + b1) * scale;
            float o2 = (acc[mi][ni][2] + b0) * scale;
            float o3 = (acc[mi][ni][3] + b1) * scale;
            if (rnd_out) { o0 = rndtf(o0); o1 = rndtf(o1); o2 = rndtf(o2); o3 = rndtf(o3); }
            float* c0 = C + (size_t)row * DD + col;
            c0[0] = o0; c0[1] = o1;
            float* c2 = C + (size_t)(row + 8) * DD + col;
            c2[0] = o2; c2[1] = o3;
        }
    }
}

// fused q/k/v projections: raw inputs -> round A fragments; W pre-rounded
__global__ __launch_bounds__(256, 3)
void projqkv_k(const float* __restrict__ query, const float* __restrict__ key,
               const float* __restrict__ value, const float* __restrict__ w_r,
               const float* __restrict__ bq, const float* __restrict__ bk,
               const float* __restrict__ bv,
               float* __restrict__ qo, float* __restrict__ ko, float* __restrict__ vo)
{
    extern __shared__ float smp[];
    int z = blockIdx.z;
    const float* A = (z == 0) ? query : (z == 1) ? key : value;
    const float* W = w_r + (size_t)z * DD * DD;
    const float* bi = (z == 0) ? bq : (z == 1) ? bk : bv;
    float* C = (z == 0) ? qo : (z == 1) ? ko : vo;
    float scale = (z == 0) ? 0.125f : 1.0f;   // fold 1/sqrt(64) into Q
    proj_body<1>(A, W, bi, C, scale, 1, smp, smp + 4608);
}

// output projection: A = o (already tf32 from av epilogue), W pre-rounded
__global__ __launch_bounds__(256, 3)
void proj_o_k(const float* __restrict__ A, const float* __restrict__ W,
              const float* __restrict__ bias, float* __restrict__ C)
{
    extern __shared__ float smp[];
    proj_body<0>(A, W, bias, C, 1.0f, 0, smp, smp + 4608);
}

// ============================================================================
// Pass A: g_rz = 1 / sum_i exp(s),  s = K_j . Q_i  (Q pre-scaled 1/8)
// block = (j-tile 128, bh) grid 384, 256 thr (2j x 4i warps, warp 64x16).
// K resident; Q streamed in 64-i chunks, DOUBLE-BUFFERED (smem unchanged
// 71680 B -> still 2 CTAs/SM; traffic unchanged vs R8).
// smem: Kt[128][68] + Qt[2][64][68] + zp[4][128]
// ============================================================================
__global__ __launch_bounds__(256, 2)
void stats_fused_k(const float* __restrict__ Qp, const float* __restrict__ Kp,
                   float* __restrict__ RZ)
{
    extern __shared__ float sm[];
    float* Kt = sm;                     // [j][d]  stride 68 (8704 floats)
    float* Qt = sm + 8704;              // [buf][i][d] stride 68 (2 x 4352)
    float* zp = sm + 2 * 8704;          // [4][128]

    int bh = blockIdx.y;
    int b = bh / HH, h = bh % HH;
    int j0 = blockIdx.x << 7;

    int t = threadIdx.x, lane = t & 31, w = t >> 5;
    int g = lane >> 2, q = lane & 3;
    int wm = (w & 1) << 6;          // 2 j-groups of 64
    int wn = (w >> 1) << 4;         // 4 i-groups of 16
    int wni = w >> 1;

    zp[t] = 0.f; zp[t + 256] = 0.f;

    // K tile resident: 128x64 = 8 f4/thr
    #pragma unroll
    for (int ch = 0; ch < 8; ch++) {
        int c = t + (ch << 8);
        int row = c >> 4, dq = (c & 15) << 2;
        cpa16(&Kt[row * 68 + dq], Kp + (size_t)(b * SS + j0 + row) * DD + h * DKK + dq);
    }
    // Q chunk 0: 64x64 = 4 f4/thr
    #pragma unroll
    for (int ch = 0; ch < 4; ch++) {
        int c = t + (ch << 8);
        int row = c >> 4, dq = (c & 15) << 2;
        cpa16(&Qt[row * 68 + dq], Qp + (size_t)(b * SS + row) * DD + h * DKK + dq);
    }
    cp_commit();

    for (int it = 0; it < 32; it++) {
        int buf = it & 1;
        if (it < 31) {   // stage Q(it+1) into other buffer (overlaps this MMA)
            #pragma unroll
            for (int ch = 0; ch < 4; ch++) {
                int c = t + (ch << 8);
                int row = c >> 4, dq = (c & 15) << 2;
                cpa16(&Qt[(buf ^ 1) * 4352 + row * 68 + dq],
                      Qp + (size_t)(b * SS + ((it + 1) << 6) + row) * DD + h * DKK + dq);
            }
            cp_commit();
            cp_wait<1>();
        } else {
            cp_wait<0>();
        }
        __syncthreads();

        float acc[4][2][4] = {};
        #pragma unroll
        for (int kk = 0; kk < DKK; kk += 8) {
            unsigned a[4][4], b2[2][2];
            #pragma unroll
            for (int mi = 0; mi < 4; mi++) {
                const float* pa = &Kt[(wm + (mi << 4) + g) * 68 + kk + q];
                a[mi][0] = __float_as_uint(pa[0]);
                a[mi][1] = __float_as_uint(pa[8 * 68]);
                a[mi][2] = __float_as_uint(pa[4]);
                a[mi][3] = __float_as_uint(pa[8 * 68 + 4]);
            }
            #pragma unroll
            for (int ni = 0; ni < 2; ni++) {
                const float* pb = &Qt[buf * 4352 + (wn + (ni << 3) + g) * 68 + kk + q];
                b2[ni][0] = __float_as_uint(pb[0]);
                b2[ni][1] = __float_as_uint(pb[4]);
            }
            #pragma unroll
            for (int mi = 0; mi < 4; mi++)
                #pragma unroll
                for (int ni = 0; ni < 2; ni++) mma8(acc[mi][ni], a[mi], b2[ni]);
        }

        // exp + reduce over i within warp tile, accumulate per-j partials
        #pragma unroll
        for (int mi = 0; mi < 4; mi++) {
            float s0 = 0.f, s1 = 0.f;
            #pragma unroll
            for (int ni = 0; ni < 2; ni++) {
                s0 += __expf(acc[mi][ni][0]) + __expf(acc[mi][ni][1]);
                s1 += __expf(acc[mi][ni][2]) + __expf(acc[mi][ni][3]);
            }
            s0 += __shfl_xor_sync(0xffffffffu, s0, 1);
            s0 += __shfl_xor_sync(0xffffffffu, s0, 2);
            s1 += __shfl_xor_sync(0xffffffffu, s1, 1);
            s1 += __shfl_xor_sync(0xffffffffu, s1, 2);
            if (q == 0) {
                zp[wni * 128 + wm + (mi << 4) + g]     += s0;
                zp[wni * 128 + wm + (mi << 4) + g + 8] += s1;
            }
        }
        __syncthreads();   // zp + Qt[buf] reads done before it+2 restage
    }

    if (t < 128) {
        float z = zp[t] + zp[128 + t] + zp[256 + t] + zp[384 + t];
        RZ[bh * SS + j0 + t] = 1.0f / z;
    }
}

// ============================================================================
// Pass B (R11, kept): O[b,i,h,d] = sum_j exp(s)*rz[j] * V[j,d]
// block = (i-tile 128, bh), 256 thr, j-loop tile 64 (32 iters), 2 CTAs/SM.
// ============================================================================
__global__ __launch_bounds__(256, 2)
void av_fused_k(const float* __restrict__ Qp, const float* __restrict__ Kp,
                const float* __restrict__ Vp, const float* __restrict__ RZ,
                float* __restrict__ O)
{
    extern __shared__ float smf[];
    float* Qt = smf;                       // [i][d]  stride 68 (8704 floats)
    float* Kt = smf + 8704;                // [j][d]  stride 68 (4352)
    float* Vt = smf + 8704 + 4352;         // [j][d]  stride 72 (4608)
    float* Ps = smf + 8704 + 4352 + 4608;  // [j][i]  stride 136 (8704)

    int bh = blockIdx.y;
    int b = bh / HH, h = bh % HH;
    int i0 = blockIdx.x << 7;

    int t = threadIdx.x, lane = t & 31, w = t >> 5;
    int g = lane >> 2, q = lane & 3;
    int wj1 = (w & 1) << 5, wi1 = (w >> 1) << 5;   // MMA1: 2j x 4i (32x32)
    int wm2 = (w & 3) << 5, wn2 = (w >> 2) << 5;   // MMA2: 4i x 2d (32x32)

    #pragma unroll
    for (int ch = 0; ch < 8; ch++) {
        int c = t + (ch << 8);
        int row = c >> 4, dq = (c & 15) << 2;
        cpa16(&Qt[row * 68 + dq], Qp + (size_t)(b * SS + i0 + row) * DD + h * DKK + dq);
    }
    #pragma unroll
    for (int ch = 0; ch < 4; ch++) {
        int c = t + (ch << 8);
        int row = c >> 4, dq = (c & 15) << 2;
        cpa16(&Kt[row * 68 + dq], Kp + (size_t)(b * SS + row) * DD + h * DKK + dq);
    }
    cp_commit();
    #pragma unroll
    for (int ch = 0; ch < 4; ch++) {
        int c = t + (ch << 8);
        int row = c >> 4, dq = (c & 15) << 2;
        cpa16(&Vt[row * 72 + dq], Vp + (size_t)(b * SS + row) * DD + h * DKK + dq);
    }
    cp_commit();

    float accO[2][4][4] = {};

    for (int it = 0; it < 32; it++) {
        int jc = it << 6;
        cp_wait<1>();
        __syncthreads();

        float acc1[2][4][4] = {};
        #pragma unroll
        for (int kk = 0; kk < DKK; kk += 8) {
            unsigned a[2][4], b2[4][2];
            #pragma unroll
            for (int mi = 0; mi < 2; mi++) {
                const float* pa = &Kt[(wj1 + (mi << 4) + g) * 68 + kk + q];
                a[mi][0] = __float_as_uint(pa[0]);
                a[mi][1] = __float_as_uint(pa[8 * 68]);
                a[mi][2] = __float_as_uint(pa[4]);
                a[mi][3] = __float_as_uint(pa[8 * 68 + 4]);
            }
            #pragma unroll
            for (int ni = 0; ni < 4; ni++) {
                const float* pb = &Qt[(wi1 + (ni << 3) + g) * 68 + kk + q];
                b2[ni][0] = __float_as_uint(pb[0]);
                b2[ni][1] = __float_as_uint(pb[4]);
            }
            #pragma unroll
            for (int mi = 0; mi < 2; mi++)
                #pragma unroll
                for (int ni = 0; ni < 4; ni++) mma8(acc1[mi][ni], a[mi], b2[ni]);
        }
        __syncthreads();

        if (it < 31) {
            #pragma unroll
            for (int ch = 0; ch < 4; ch++) {
                int c = t + (ch << 8);
                int row = c >> 4, dq = (c & 15) << 2;
                cpa16(&Kt[row * 68 + dq],
                      Kp + (size_t)(b * SS + jc + 64 + row) * DD + h * DKK + dq);
            }
        }

        #pragma unroll
        for (int mi = 0; mi < 2; mi++) {
            int r0 = wj1 + (mi << 4) + g;
            float rz0 = RZ[bh * SS + jc + r0];
            float rz1 = RZ[bh * SS + jc + r0 + 8];
            #pragma unroll
            for (int ni = 0; ni < 4; ni++) {
                int col = wi1 + (ni << 3) + (q << 1);
                float2 p0 = make_float2(rndtf(__expf(acc1[mi][ni][0]) * rz0),
                                        rndtf(__expf(acc1[mi][ni][1]) * rz0));
                float2 p1 = make_float2(rndtf(__expf(acc1[mi][ni][2]) * rz1),
                                        rndtf(__expf(acc1[mi][ni][3]) * rz1));
                *(float2*)&Ps[r0 * 136 + col]       = p0;
                *(float2*)&Ps[(r0 + 8) * 136 + col] = p1;
            }
        }
        cp_wait<0>();
        cp_commit();
        __syncthreads();

        #pragma unroll
        for (int kk = 0; kk < 64; kk += 8) {
            unsigned a[2][4], b2[4][2];
            #pragma unroll
            for (int mi = 0; mi < 2; mi++) {
                const float* pa = &Ps[(kk + q) * 136 + wm2 + (mi << 4) + g];
                a[mi][0] = __float_as_uint(pa[0]);
                a[mi][1] = __float_as_uint(pa[8]);
                a[mi][2] = __float_as_uint(pa[4 * 136]);
                a[mi][3] = __float_as_uint(pa[4 * 136 + 8]);
            }
            #pragma unroll
            for (int ni = 0; ni < 4; ni++) {
                const float* pb = &Vt[(kk + q) * 72 + wn2 + (ni << 3) + g];
                b2[ni][0] = __float_as_uint(pb[0]);
                b2[ni][1] = __float_as_uint(pb[4 * 72]);
            }
            #pragma unroll
            for (int mi = 0; mi < 2; mi++)
                #pragma unroll
                for (int ni = 0; ni < 4; ni++) mma8(accO[mi][ni], a[mi], b2[ni]);
        }
        __syncthreads();

        if (it < 31) {
            #pragma unroll
            for (int ch = 0; ch < 4; ch++) {
                int c = t + (ch << 8);
                int row = c >> 4, dq = (c & 15) << 2;
                cpa16(&Vt[row * 72 + dq],
                      Vp + (size_t)(b * SS + jc + 64 + row) * DD + h * DKK + dq);
            }
            cp_commit();
        }
    }

    #pragma unroll
    for (int mi = 0; mi < 2; mi++) {
        #pragma unroll
        for (int ni = 0; ni < 4; ni++) {
            int row = i0 + wm2 + (mi << 4) + g;
            int col = h * DKK + wn2 + (ni << 3) + (q << 1);
            float2 o0 = make_float2(rndtf(accO[mi][ni][0]), rndtf(accO[mi][ni][1]));
            float2 o1 = make_float2(rndtf(accO[mi][ni][2]), rndtf(accO[mi][ni][3]));
            *(float2*)&O[(size_t)(b * SS + row) * DD + col]     = o0;
            *(float2*)&O[(size_t)(b * SS + row + 8) * DD + col] = o1;
        }
    }
}

// ---------------- launch -----------------------------------------------------
extern "C" void kernel_launch(void* const* d_in, const int* in_sizes, int n_in,
                              void* d_out, int out_size)
{
    const float* query = (const float*)d_in[0];
    const float* key   = (const float*)d_in[1];
    const float* value = (const float*)d_in[2];
    const float* Wq = (const float*)d_in[3];
    const float* bq = (const float*)d_in[4];
    const float* Wk = (const float*)d_in[5];
    const float* bk = (const float*)d_in[6];
    const float* Wv = (const float*)d_in[7];
    const float* bv = (const float*)d_in[8];
    const float* Wo = (const float*)d_in[9];
    const float* bo = (const float*)d_in[10];
    float* out = (float*)d_out;

    float *q, *k, *v, *o, *rz, *wr;
    cudaGetSymbolAddress((void**)&q,  g_q);
    cudaGetSymbolAddress((void**)&k,  g_k);
    cudaGetSymbolAddress((void**)&v,  g_v);
    cudaGetSymbolAddress((void**)&o,  g_o);
    cudaGetSymbolAddress((void**)&rz, g_rz);
    cudaGetSymbolAddress((void**)&wr, g_w);

    const int SMEM_P = (2 * 64 * 36 + 2 * 32 * 136) * 4;          // 53248
    const int SMEM_A = (2 * 8704 + 512) * 4;                      // 71680
    const int SMEM_B = (8704 + 4352 + 4608 + 8704) * 4;           // 105472
    cudaFuncSetAttribute(projqkv_k,     cudaFuncAttributeMaxDynamicSharedMemorySize, SMEM_P);
    cudaFuncSetAttribute(proj_o_k,      cudaFuncAttributeMaxDynamicSharedMemorySize, SMEM_P);
    cudaFuncSetAttribute(stats_fused_k, cudaFuncAttributeMaxDynamicSharedMemorySize, SMEM_A);
    cudaFuncSetAttribute(av_fused_k,    cudaFuncAttributeMaxDynamicSharedMemorySize, SMEM_B);

    // weights prepass (tiny): 4 x 768x768
    round_weights_k<<<dim3((DD * DD / 4 + 255) / 256, 4), 256>>>(Wq, Wk, Wv, Wo, wr);

    // fused q/k/v projections: grid (6, 64, 3)
    projqkv_k<<<dim3(DD / 128, MM / 64, 3), 256, SMEM_P>>>(query, key, value, wr,
                                                           bq, bk, bv, q, k, v);

    stats_fused_k<<<dim3(SS / 128, BB * HH), 256, SMEM_A>>>(q, k, rz);

    av_fused_k<<<dim3(SS / 128, BB * HH), 256, SMEM_B>>>(q, k, v, rz, o);

    proj_o_k<<<dim3(DD / 128, MM / 64), 256, SMEM_P>>>(o, wr + (size_t)3 * DD * DD, bo, out);
}

// round 13
// speedup vs baseline: 1.0370x; 1.0370x over previous
#include <cuda_runtime.h>

#define BB 2
#define SS 2048
#define DD 768
#define HH 12
#define DKK 64
#define MM (BB*SS)   // 4096

// ---------------- scratch (static device globals) ---------------------------
__device__ float g_q[MM * DD];
__device__ float g_k[MM * DD];
__device__ float g_v[MM * DD];
__device__ float g_o[MM * DD];
__device__ float g_rz[BB * HH * SS];   // 1 / sum_i exp(s[b,h,j,i])
__device__ float g_w [4 * DD * DD];    // tf32-rounded Wq/Wk/Wv/Wo

// ---------------- helpers ----------------------------------------------------
__device__ __forceinline__ void cpa16(void* s, const void* g) {
    unsigned sa = (unsigned)__cvta_generic_to_shared(s);
    asm volatile("cp.async.ca.shared.global [%0], [%1], 16;\n" :: "r"(sa), "l"(g));
}
__device__ __forceinline__ void cp_commit() { asm volatile("cp.async.commit_group;\n"); }
template<int N> __device__ __forceinline__ void cp_wait() {
    asm volatile("cp.async.wait_group %0;\n" :: "n"(N));
}
__device__ __forceinline__ unsigned f2tf(float f) {
    unsigned u;
    asm("cvt.rna.tf32.f32 %0, %1;" : "=r"(u) : "f"(f));
    return u;
}
__device__ __forceinline__ float rndtf(float f) { return __uint_as_float(f2tf(f)); }

// D += A(16x8) * B(8x8), tf32, f32 accum
__device__ __forceinline__ void mma8(float c[4], const unsigned a[4], const unsigned b[2]) {
    asm volatile(
        "mma.sync.aligned.m16n8k8.row.col.f32.tf32.tf32.f32 "
        "{%0,%1,%2,%3}, {%4,%5,%6,%7}, {%8,%9}, {%0,%1,%2,%3};"
        : "+f"(c[0]), "+f"(c[1]), "+f"(c[2]), "+f"(c[3])
        : "r"(a[0]), "r"(a[1]), "r"(a[2]), "r"(a[3]), "r"(b[0]), "r"(b[1]));
}

// ============================================================================
// Weights tf32 pre-rounding (9.4 MB traffic, one launch)
// ============================================================================
__global__ void round_weights_k(const float* __restrict__ wq,
                                const float* __restrict__ wk,
                                const float* __restrict__ wv,
                                const float* __restrict__ wo,
                                float* __restrict__ dst)
{
    const float* src = (blockIdx.y == 0) ? wq : (blockIdx.y == 1) ? wk
                     : (blockIdx.y == 2) ? wv : wo;
    float* d = dst + (size_t)blockIdx.y * DD * DD;
    int idx = (blockIdx.x * 256 + threadIdx.x) << 2;
    if (idx < DD * DD) {
        float4 x = *(const float4*)(src + idx);
        x.x = rndtf(x.x); x.y = rndtf(x.y); x.z = rndtf(x.z); x.w = rndtf(x.w);
        *(float4*)(d + idx) = x;
    }
}

// ============================================================================
// Projection GEMM body: C = ((A @ W) + bias) * scale
// 64m x 128n tile, BK=32 (24 iters), 256 thr (2x4 warps, warp 32x32).
// W is PRE-ROUNDED. RND_A=1 rounds A fragments (raw inputs); 0 = already tf32.
// Dynamic smem 53248 B -> 3 CTAs/SM.
// ============================================================================
#define PAS(buf,m,k)  As[(buf)*2304 + (m)*36 + (k)]
#define PBS(buf,k,n)  Bs[(buf)*4352 + (k)*136 + (n)]

template<int RND_A>
__device__ __forceinline__
void proj_body(const float* __restrict__ A, const float* __restrict__ W,
               const float* __restrict__ bias, float* __restrict__ C,
               float scale, int rnd_out, float* As, float* Bs)
{
    int t = threadIdx.x, lane = t & 31, w = t >> 5;
    int g = lane >> 2, q = lane & 3;
    int wm = (w & 1) << 5, wn = (w >> 1) << 5;
    int m0 = blockIdx.y << 6, n0 = blockIdx.x << 7;

    {
        #pragma unroll
        for (int ch = 0; ch < 2; ch++) {
            int c = t + (ch << 8);
            int ar = c >> 3, akq = (c & 7) << 2;
            cpa16(&PAS(0, ar, akq), A + (size_t)(m0 + ar) * DD + akq);
        }
        #pragma unroll
        for (int ch = 0; ch < 4; ch++) {
            int c = t + (ch << 8);
            int br = c >> 5, bnq = (c & 31) << 2;
            cpa16(&PBS(0, br, bnq), W + (size_t)br * DD + n0 + bnq);
        }
    }
    cp_commit();

    float acc[2][4][4] = {};

    for (int it = 0; it < 24; it++) {
        int buf = it & 1;
        if (it < 23) {
            int k0 = (it + 1) << 5;
            #pragma unroll
            for (int ch = 0; ch < 2; ch++) {
                int c = t + (ch << 8);
                int ar = c >> 3, akq = (c & 7) << 2;
                cpa16(&PAS(buf ^ 1, ar, akq), A + (size_t)(m0 + ar) * DD + k0 + akq);
            }
            #pragma unroll
            for (int ch = 0; ch < 4; ch++) {
                int c = t + (ch << 8);
                int br = c >> 5, bnq = (c & 31) << 2;
                cpa16(&PBS(buf ^ 1, br, bnq), W + (size_t)(k0 + br) * DD + n0 + bnq);
            }
            cp_commit();
            cp_wait<1>();
        } else {
            cp_wait<0>();
        }
        __syncthreads();

        #pragma unroll
        for (int kk = 0; kk < 32; kk += 8) {
            unsigned a[2][4], b2[4][2];
            #pragma unroll
            for (int mi = 0; mi < 2; mi++) {
                const float* pa = &PAS(buf, wm + (mi << 4) + g, kk + q);
                if (RND_A) {
                    a[mi][0] = f2tf(pa[0]);
                    a[mi][1] = f2tf(pa[8 * 36]);
                    a[mi][2] = f2tf(pa[4]);
                    a[mi][3] = f2tf(pa[8 * 36 + 4]);
                } else {
                    a[mi][0] = __float_as_uint(pa[0]);
                    a[mi][1] = __float_as_uint(pa[8 * 36]);
                    a[mi][2] = __float_as_uint(pa[4]);
                    a[mi][3] = __float_as_uint(pa[8 * 36 + 4]);
                }
            }
            #pragma unroll
            for (int ni = 0; ni < 4; ni++) {
                const float* pb = &PBS(buf, kk + q, wn + (ni << 3) + g);
                b2[ni][0] = __float_as_uint(pb[0]);
                b2[ni][1] = __float_as_uint(pb[4 * 136]);
            }
            #pragma unroll
            for (int mi = 0; mi < 2; mi++)
                #pragma unroll
                for (int ni = 0; ni < 4; ni++) mma8(acc[mi][ni], a[mi], b2[ni]);
        }
        __syncthreads();
    }

    #pragma unroll
    for (int ni = 0; ni < 4; ni++) {
        int col = n0 + wn + (ni << 3) + (q << 1);
        float b0 = bias[col], b1 = bias[col + 1];
        #pragma unroll
        for (int mi = 0; mi < 2; mi++) {
            int row = m0 + wm + (mi << 4) + g;
            float o0 = (acc[mi][ni][0] + b0) * scale;
            float o1 = (acc[mi][ni][1] + b1) * scale;
            float o2 = (acc[mi][ni][2] + b0) * scale;
            float o3 = (acc[mi][ni][3] + b1) * scale;
            if (rnd_out) { o0 = rndtf(o0); o1 = rndtf(o1); o2 = rndtf(o2); o3 = rndtf(o3); }
            float* c0 = C + (size_t)row * DD + col;
            c0[0] = o0; c0[1] = o1;
            float* c2 = C + (size_t)(row + 8) * DD + col;
            c2[0] = o2; c2[1] = o3;
        }
    }
}

// fused q/k/v projections: raw inputs -> round A fragments; W pre-rounded
__global__ __launch_bounds__(256, 3)
void projqkv_k(const float* __restrict__ query, const float* __restrict__ key,
               const float* __restrict__ value, const float* __restrict__ w_r,
               const float* __restrict__ bq, const float* __restrict__ bk,
               const float* __restrict__ bv,
               float* __restrict__ qo, float* __restrict__ ko, float* __restrict__ vo)
{
    extern __shared__ float smp[];
    int z = blockIdx.z;
    const float* A = (z == 0) ? query : (z == 1) ? key : value;
    const float* W = w_r + (size_t)z * DD * DD;
    const float* bi = (z == 0) ? bq : (z == 1) ? bk : bv;
    float* C = (z == 0) ? qo : (z == 1) ? ko : vo;
    float scale = (z == 0) ? 0.125f : 1.0f;   // fold 1/sqrt(64) into Q
    proj_body<1>(A, W, bi, C, scale, 1, smp, smp + 4608);
}

// output projection: A = o (already tf32 from av epilogue), W pre-rounded
__global__ __launch_bounds__(256, 3)
void proj_o_k(const float* __restrict__ A, const float* __restrict__ W,
              const float* __restrict__ bias, float* __restrict__ C)
{
    extern __shared__ float smp[];
    proj_body<0>(A, W, bias, C, 1.0f, 0, smp, smp + 4608);
}

// ============================================================================
// Pass A (R8 config, best measured 98.5us): g_rz = 1 / sum_i exp(s)
// block = (j-tile 128, bh) grid 384, 256 thr (2j x 4i warps, warp 64x32).
// K resident, Q i-tiles (128) single-buffered. smem 71680 B -> 2 CTAs/SM.
// ============================================================================
__global__ __launch_bounds__(256, 2)
void stats_fused_k(const float* __restrict__ Qp, const float* __restrict__ Kp,
                   float* __restrict__ RZ)
{
    extern __shared__ float sm[];
    float* Kt = sm;                     // [j][d]  stride 68
    float* Qt = sm + 8704;              // [i][d]  stride 68
    float* zp = sm + 2 * 8704;          // [4][128]

    int bh = blockIdx.y;
    int b = bh / HH, h = bh % HH;
    int j0 = blockIdx.x << 7;

    int t = threadIdx.x, lane = t & 31, w = t >> 5;
    int g = lane >> 2, q = lane & 3;
    int wm = (w & 1) << 6, wn = (w >> 1) << 5;
    int wni = w >> 1;

    zp[t] = 0.f; zp[t + 256] = 0.f;

    #pragma unroll
    for (int ch = 0; ch < 8; ch++) {
        int c = t + (ch << 8);
        int row = c >> 4, dq = (c & 15) << 2;
        cpa16(&Kt[row * 68 + dq], Kp + (size_t)(b * SS + j0 + row) * DD + h * DKK + dq);
    }
    cp_commit();

    for (int it = 0; it < 16; it++) {
        #pragma unroll
        for (int ch = 0; ch < 8; ch++) {
            int c = t + (ch << 8);
            int row = c >> 4, dq = (c & 15) << 2;
            cpa16(&Qt[row * 68 + dq],
                  Qp + (size_t)(b * SS + (it << 7) + row) * DD + h * DKK + dq);
        }
        cp_commit();
        cp_wait<0>();
        __syncthreads();

        float acc[4][4][4] = {};
        #pragma unroll
        for (int kk = 0; kk < DKK; kk += 8) {
            unsigned a[4][4], b2[4][2];
            #pragma unroll
            for (int mi = 0; mi < 4; mi++) {
                const float* pa = &Kt[(wm + (mi << 4) + g) * 68 + kk + q];
                a[mi][0] = __float_as_uint(pa[0]);
                a[mi][1] = __float_as_uint(pa[8 * 68]);
                a[mi][2] = __float_as_uint(pa[4]);
                a[mi][3] = __float_as_uint(pa[8 * 68 + 4]);
            }
            #pragma unroll
            for (int ni = 0; ni < 4; ni++) {
                const float* pb = &Qt[(wn + (ni << 3) + g) * 68 + kk + q];
                b2[ni][0] = __float_as_uint(pb[0]);
                b2[ni][1] = __float_as_uint(pb[4]);
            }
            #pragma unroll
            for (int mi = 0; mi < 4; mi++)
                #pragma unroll
                for (int ni = 0; ni < 4; ni++) mma8(acc[mi][ni], a[mi], b2[ni]);
        }

        #pragma unroll
        for (int mi = 0; mi < 4; mi++) {
            float s0 = 0.f, s1 = 0.f;
            #pragma unroll
            for (int ni = 0; ni < 4; ni++) {
                s0 += __expf(acc[mi][ni][0]) + __expf(acc[mi][ni][1]);
                s1 += __expf(acc[mi][ni][2]) + __expf(acc[mi][ni][3]);
            }
            s0 += __shfl_xor_sync(0xffffffffu, s0, 1);
            s0 += __shfl_xor_sync(0xffffffffu, s0, 2);
            s1 += __shfl_xor_sync(0xffffffffu, s1, 1);
            s1 += __shfl_xor_sync(0xffffffffu, s1, 2);
            if (q == 0) {
                zp[wni * 128 + wm + (mi << 4) + g]     += s0;
                zp[wni * 128 + wm + (mi << 4) + g + 8] += s1;
            }
        }
        __syncthreads();
    }

    if (t < 128) {
        float z = zp[t] + zp[128 + t] + zp[256 + t] + zp[384 + t];
        RZ[bh * SS + j0 + t] = 1.0f / z;
    }
}

// ============================================================================
// Pass B (R11 config + RZ prefetch hoist): O = sum_j exp(s)*rz[j] * V[j,d]
// block = (i-tile 128, bh), 256 thr, j-loop tile 64 (32 iters), 2 CTAs/SM.
// ============================================================================
__global__ __launch_bounds__(256, 2)
void av_fused_k(const float* __restrict__ Qp, const float* __restrict__ Kp,
                const float* __restrict__ Vp, const float* __restrict__ RZ,
                float* __restrict__ O)
{
    extern __shared__ float smf[];
    float* Qt = smf;                       // [i][d]  stride 68 (8704 floats)
    float* Kt = smf + 8704;                // [j][d]  stride 68 (4352)
    float* Vt = smf + 8704 + 4352;         // [j][d]  stride 72 (4608)
    float* Ps = smf + 8704 + 4352 + 4608;  // [j][i]  stride 136 (8704)

    int bh = blockIdx.y;
    int b = bh / HH, h = bh % HH;
    int i0 = blockIdx.x << 7;

    int t = threadIdx.x, lane = t & 31, w = t >> 5;
    int g = lane >> 2, q = lane & 3;
    int wj1 = (w & 1) << 5, wi1 = (w >> 1) << 5;   // MMA1: 2j x 4i (32x32)
    int wm2 = (w & 3) << 5, wn2 = (w >> 2) << 5;   // MMA2: 4i x 2d (32x32)

    #pragma unroll
    for (int ch = 0; ch < 8; ch++) {
        int c = t + (ch << 8);
        int row = c >> 4, dq = (c & 15) << 2;
        cpa16(&Qt[row * 68 + dq], Qp + (size_t)(b * SS + i0 + row) * DD + h * DKK + dq);
    }
    #pragma unroll
    for (int ch = 0; ch < 4; ch++) {
        int c = t + (ch << 8);
        int row = c >> 4, dq = (c & 15) << 2;
        cpa16(&Kt[row * 68 + dq], Kp + (size_t)(b * SS + row) * DD + h * DKK + dq);
    }
    cp_commit();
    #pragma unroll
    for (int ch = 0; ch < 4; ch++) {
        int c = t + (ch << 8);
        int row = c >> 4, dq = (c & 15) << 2;
        cpa16(&Vt[row * 72 + dq], Vp + (size_t)(b * SS + row) * DD + h * DKK + dq);
    }
    cp_commit();

    float accO[2][4][4] = {};

    for (int it = 0; it < 32; it++) {
        int jc = it << 6;

        // prefetch RZ for this tile's warp rows (hides LDG behind K-wait+MMA1)
        float rzv[2][2];
        #pragma unroll
        for (int mi = 0; mi < 2; mi++) {
            int r0 = wj1 + (mi << 4) + g;
            rzv[mi][0] = RZ[bh * SS + jc + r0];
            rzv[mi][1] = RZ[bh * SS + jc + r0 + 8];
        }

        cp_wait<1>();      // K(it) ready (V(it) may still be in flight)
        __syncthreads();

        float acc1[2][4][4] = {};
        #pragma unroll
        for (int kk = 0; kk < DKK; kk += 8) {
            unsigned a[2][4], b2[4][2];
            #pragma unroll
            for (int mi = 0; mi < 2; mi++) {
                const float* pa = &Kt[(wj1 + (mi << 4) + g) * 68 + kk + q];
                a[mi][0] = __float_as_uint(pa[0]);
                a[mi][1] = __float_as_uint(pa[8 * 68]);
                a[mi][2] = __float_as_uint(pa[4]);
                a[mi][3] = __float_as_uint(pa[8 * 68 + 4]);
            }
            #pragma unroll
            for (int ni = 0; ni < 4; ni++) {
                const float* pb = &Qt[(wi1 + (ni << 3) + g) * 68 + kk + q];
                b2[ni][0] = __float_as_uint(pb[0]);
                b2[ni][1] = __float_as_uint(pb[4]);
            }
            #pragma unroll
            for (int mi = 0; mi < 2; mi++)
                #pragma unroll
                for (int ni = 0; ni < 4; ni++) mma8(acc1[mi][ni], a[mi], b2[ni]);
        }
        __syncthreads();   // Kt reads done

        if (it < 31) {     // prefetch K(it+1) (uncommitted yet)
            #pragma unroll
            for (int ch = 0; ch < 4; ch++) {
                int c = t + (ch << 8);
                int row = c >> 4, dq = (c & 15) << 2;
                cpa16(&Kt[row * 68 + dq],
                      Kp + (size_t)(b * SS + jc + 64 + row) * DD + h * DKK + dq);
            }
        }

        // ---- P = round_tf32( exp(s) * rz[j] ) -> Ps[j][i] ----
        #pragma unroll
        for (int mi = 0; mi < 2; mi++) {
            int r0 = wj1 + (mi << 4) + g;
            float rz0 = rzv[mi][0], rz1 = rzv[mi][1];
            #pragma unroll
            for (int ni = 0; ni < 4; ni++) {
                int col = wi1 + (ni << 3) + (q << 1);
                float2 p0 = make_float2(rndtf(__expf(acc1[mi][ni][0]) * rz0),
                                        rndtf(__expf(acc1[mi][ni][1]) * rz0));
                float2 p1 = make_float2(rndtf(__expf(acc1[mi][ni][2]) * rz1),
                                        rndtf(__expf(acc1[mi][ni][3]) * rz1));
                *(float2*)&Ps[r0 * 136 + col]       = p0;
                *(float2*)&Ps[(r0 + 8) * 136 + col] = p1;
            }
        }
        cp_wait<0>();      // V(it) ready (committed groups only)
        cp_commit();       // close K(it+1) group
        __syncthreads();   // Ps visible + Vt ready

        #pragma unroll
        for (int kk = 0; kk < 64; kk += 8) {
            unsigned a[2][4], b2[4][2];
            #pragma unroll
            for (int mi = 0; mi < 2; mi++) {
                const float* pa = &Ps[(kk + q) * 136 + wm2 + (mi << 4) + g];
                a[mi][0] = __float_as_uint(pa[0]);
                a[mi][1] = __float_as_uint(pa[8]);
                a[mi][2] = __float_as_uint(pa[4 * 136]);
                a[mi][3] = __float_as_uint(pa[4 * 136 + 8]);
            }
            #pragma unroll
            for (int ni = 0; ni < 4; ni++) {
                const float* pb = &Vt[(kk + q) * 72 + wn2 + (ni << 3) + g];
                b2[ni][0] = __float_as_uint(pb[0]);
                b2[ni][1] = __float_as_uint(pb[4 * 72]);
            }
            #pragma unroll
            for (int mi = 0; mi < 2; mi++)
                #pragma unroll
                for (int ni = 0; ni < 4; ni++) mma8(accO[mi][ni], a[mi], b2[ni]);
        }
        __syncthreads();   // Vt reads done

        if (it < 31) {     // prefetch V(it+1)
            #pragma unroll
            for (int ch = 0; ch < 4; ch++) {
                int c = t + (ch << 8);
                int row = c >> 4, dq = (c & 15) << 2;
                cpa16(&Vt[row * 72 + dq],
                      Vp + (size_t)(b * SS + jc + 64 + row) * DD + h * DKK + dq);
            }
            cp_commit();
        }
    }

    // epilogue: O rounded to tf32 (consumed by final projection)
    #pragma unroll
    for (int mi = 0; mi < 2; mi++) {
        #pragma unroll
        for (int ni = 0; ni < 4; ni++) {
            int row = i0 + wm2 + (mi << 4) + g;
            int col = h * DKK + wn2 + (ni << 3) + (q << 1);
            float2 o0 = make_float2(rndtf(accO[mi][ni][0]), rndtf(accO[mi][ni][1]));
            float2 o1 = make_float2(rndtf(accO[mi][ni][2]), rndtf(accO[mi][ni][3]));
            *(float2*)&O[(size_t)(b * SS + row) * DD + col]     = o0;
            *(float2*)&O[(size_t)(b * SS + row + 8) * DD + col] = o1;
        }
    }
}

// ---------------- launch -----------------------------------------------------
extern "C" void kernel_launch(void* const* d_in, const int* in_sizes, int n_in,
                              void* d_out, int out_size)
{
    const float* query = (const float*)d_in[0];
    const float* key   = (const float*)d_in[1];
    const float* value = (const float*)d_in[2];
    const float* Wq = (const float*)d_in[3];
    const float* bq = (const float*)d_in[4];
    const float* Wk = (const float*)d_in[5];
    const float* bk = (const float*)d_in[6];
    const float* Wv = (const float*)d_in[7];
    const float* bv = (const float*)d_in[8];
    const float* Wo = (const float*)d_in[9];
    const float* bo = (const float*)d_in[10];
    float* out = (float*)d_out;

    float *q, *k, *v, *o, *rz, *wr;
    cudaGetSymbolAddress((void**)&q,  g_q);
    cudaGetSymbolAddress((void**)&k,  g_k);
    cudaGetSymbolAddress((void**)&v,  g_v);
    cudaGetSymbolAddress((void**)&o,  g_o);
    cudaGetSymbolAddress((void**)&rz, g_rz);
    cudaGetSymbolAddress((void**)&wr, g_w);

    const int SMEM_P = (2 * 64 * 36 + 2 * 32 * 136) * 4;          // 53248
    const int SMEM_A = (2 * 8704 + 512) * 4;                      // 71680
    const int SMEM_B = (8704 + 4352 + 4608 + 8704) * 4;           // 105472
    cudaFuncSetAttribute(projqkv_k,     cudaFuncAttributeMaxDynamicSharedMemorySize, SMEM_P);
    cudaFuncSetAttribute(proj_o_k,      cudaFuncAttributeMaxDynamicSharedMemorySize, SMEM_P);
    cudaFuncSetAttribute(stats_fused_k, cudaFuncAttributeMaxDynamicSharedMemorySize, SMEM_A);
    cudaFuncSetAttribute(av_fused_k,    cudaFuncAttributeMaxDynamicSharedMemorySize, SMEM_B);

    // weights prepass (tiny): 4 x 768x768
    round_weights_k<<<dim3((DD * DD / 4 + 255) / 256, 4), 256>>>(Wq, Wk, Wv, Wo, wr);

    // fused q/k/v projections: grid (6, 64, 3)
    projqkv_k<<<dim3(DD / 128, MM / 64, 3), 256, SMEM_P>>>(query, key, value, wr,
                                                           bq, bk, bv, q, k, v);

    stats_fused_k<<<dim3(SS / 128, BB * HH), 256, SMEM_A>>>(q, k, rz);

    av_fused_k<<<dim3(SS / 128, BB * HH), 256, SMEM_B>>>(q, k, v, rz, o);

    proj_o_k<<<dim3(DD / 128, MM / 64), 256, SMEM_P>>>(o, wr + (size_t)3 * DD * DD, bo, out);
}

// round 14
// speedup vs baseline: 1.2289x; 1.1851x over previous
#include <cuda_runtime.h>
#include <cuda_fp16.h>

#define BB 2
#define SS 2048
#define DD 768
#define HH 12
#define DKK 64
#define MM (BB*SS)   // 4096

// ---------------- scratch (static device globals) ---------------------------
__device__ __half g_qh[MM * DD];       // fp16 q (pre-scaled 1/8)
__device__ __half g_kh[MM * DD];       // fp16 k
__device__ float  g_v [MM * DD];       // tf32-rounded v
__device__ float  g_o [MM * DD];       // tf32-rounded attention output
__device__ float  g_rz[BB * HH * SS];  // 1 / sum_i exp(s[b,h,j,i])
__device__ float  g_w [4 * DD * DD];   // tf32-rounded Wq/Wk/Wv/Wo

// ---------------- helpers ----------------------------------------------------
__device__ __forceinline__ void cpa16(void* s, const void* g) {
    unsigned sa = (unsigned)__cvta_generic_to_shared(s);
    asm volatile("cp.async.ca.shared.global [%0], [%1], 16;\n" :: "r"(sa), "l"(g));
}
__device__ __forceinline__ void cp_commit() { asm volatile("cp.async.commit_group;\n"); }
template<int N> __device__ __forceinline__ void cp_wait() {
    asm volatile("cp.async.wait_group %0;\n" :: "n"(N));
}
__device__ __forceinline__ unsigned f2tf(float f) {
    unsigned u;
    asm("cvt.rna.tf32.f32 %0, %1;" : "=r"(u) : "f"(f));
    return u;
}
__device__ __forceinline__ float rndtf(float f) { return __uint_as_float(f2tf(f)); }

// tf32: D += A(16x8) * B(8x8)
__device__ __forceinline__ void mma8(float c[4], const unsigned a[4], const unsigned b[2]) {
    asm volatile(
        "mma.sync.aligned.m16n8k8.row.col.f32.tf32.tf32.f32 "
        "{%0,%1,%2,%3}, {%4,%5,%6,%7}, {%8,%9}, {%0,%1,%2,%3};"
        : "+f"(c[0]), "+f"(c[1]), "+f"(c[2]), "+f"(c[3])
        : "r"(a[0]), "r"(a[1]), "r"(a[2]), "r"(a[3]), "r"(b[0]), "r"(b[1]));
}
// fp16: D += A(16x16) * B(16x8), f32 accum
__device__ __forceinline__ void mma16(float c[4], const unsigned a[4], const unsigned b[2]) {
    asm volatile(
        "mma.sync.aligned.m16n8k16.row.col.f32.f16.f16.f32 "
        "{%0,%1,%2,%3}, {%4,%5,%6,%7}, {%8,%9}, {%0,%1,%2,%3};"
        : "+f"(c[0]), "+f"(c[1]), "+f"(c[2]), "+f"(c[3])
        : "r"(a[0]), "r"(a[1]), "r"(a[2]), "r"(a[3]), "r"(b[0]), "r"(b[1]));
}

// ============================================================================
// Weights tf32 pre-rounding
// ============================================================================
__global__ void round_weights_k(const float* __restrict__ wq,
                                const float* __restrict__ wk,
                                const float* __restrict__ wv,
                                const float* __restrict__ wo,
                                float* __restrict__ dst)
{
    const float* src = (blockIdx.y == 0) ? wq : (blockIdx.y == 1) ? wk
                     : (blockIdx.y == 2) ? wv : wo;
    float* d = dst + (size_t)blockIdx.y * DD * DD;
    int idx = (blockIdx.x * 256 + threadIdx.x) << 2;
    if (idx < DD * DD) {
        float4 x = *(const float4*)(src + idx);
        x.x = rndtf(x.x); x.y = rndtf(x.y); x.z = rndtf(x.z); x.w = rndtf(x.w);
        *(float4*)(d + idx) = x;
    }
}

// ============================================================================
// Projection GEMM body: out = ((A @ W) + bias) * scale
// 64m x 128n tile, BK=32 (24 iters), 256 thr (2x4 warps, warp 32x32).
// W PRE-ROUNDED tf32. RND_A rounds A fragments. OUT_HALF: emit __half.
// ============================================================================
#define PAS(buf,m,k)  As[(buf)*2304 + (m)*36 + (k)]
#define PBS(buf,k,n)  Bs[(buf)*4352 + (k)*136 + (n)]

template<int RND_A, int OUT_HALF>
__device__ __forceinline__
void proj_body(const float* __restrict__ A, const float* __restrict__ W,
               const float* __restrict__ bias, void* __restrict__ Cout,
               float scale, int rnd_out, float* As, float* Bs)
{
    int t = threadIdx.x, lane = t & 31, w = t >> 5;
    int g = lane >> 2, q = lane & 3;
    int wm = (w & 1) << 5, wn = (w >> 1) << 5;
    int m0 = blockIdx.y << 6, n0 = blockIdx.x << 7;

    {
        #pragma unroll
        for (int ch = 0; ch < 2; ch++) {
            int c = t + (ch << 8);
            int ar = c >> 3, akq = (c & 7) << 2;
            cpa16(&PAS(0, ar, akq), A + (size_t)(m0 + ar) * DD + akq);
        }
        #pragma unroll
        for (int ch = 0; ch < 4; ch++) {
            int c = t + (ch << 8);
            int br = c >> 5, bnq = (c & 31) << 2;
            cpa16(&PBS(0, br, bnq), W + (size_t)br * DD + n0 + bnq);
        }
    }
    cp_commit();

    float acc[2][4][4] = {};

    for (int it = 0; it < 24; it++) {
        int buf = it & 1;
        if (it < 23) {
            int k0 = (it + 1) << 5;
            #pragma unroll
            for (int ch = 0; ch < 2; ch++) {
                int c = t + (ch << 8);
                int ar = c >> 3, akq = (c & 7) << 2;
                cpa16(&PAS(buf ^ 1, ar, akq), A + (size_t)(m0 + ar) * DD + k0 + akq);
            }
            #pragma unroll
            for (int ch = 0; ch < 4; ch++) {
                int c = t + (ch << 8);
                int br = c >> 5, bnq = (c & 31) << 2;
                cpa16(&PBS(buf ^ 1, br, bnq), W + (size_t)(k0 + br) * DD + n0 + bnq);
            }
            cp_commit();
            cp_wait<1>();
        } else {
            cp_wait<0>();
        }
        __syncthreads();

        #pragma unroll
        for (int kk = 0; kk < 32; kk += 8) {
            unsigned a[2][4], b2[4][2];
            #pragma unroll
            for (int mi = 0; mi < 2; mi++) {
                const float* pa = &PAS(buf, wm + (mi << 4) + g, kk + q);
                if (RND_A) {
                    a[mi][0] = f2tf(pa[0]);
                    a[mi][1] = f2tf(pa[8 * 36]);
                    a[mi][2] = f2tf(pa[4]);
                    a[mi][3] = f2tf(pa[8 * 36 + 4]);
                } else {
                    a[mi][0] = __float_as_uint(pa[0]);
                    a[mi][1] = __float_as_uint(pa[8 * 36]);
                    a[mi][2] = __float_as_uint(pa[4]);
                    a[mi][3] = __float_as_uint(pa[8 * 36 + 4]);
                }
            }
            #pragma unroll
            for (int ni = 0; ni < 4; ni++) {
                const float* pb = &PBS(buf, kk + q, wn + (ni << 3) + g);
                b2[ni][0] = __float_as_uint(pb[0]);
                b2[ni][1] = __float_as_uint(pb[4 * 136]);
            }
            #pragma unroll
            for (int mi = 0; mi < 2; mi++)
                #pragma unroll
                for (int ni = 0; ni < 4; ni++) mma8(acc[mi][ni], a[mi], b2[ni]);
        }
        __syncthreads();
    }

    #pragma unroll
    for (int ni = 0; ni < 4; ni++) {
        int col = n0 + wn + (ni << 3) + (q << 1);
        float b0 = bias[col], b1 = bias[col + 1];
        #pragma unroll
        for (int mi = 0; mi < 2; mi++) {
            int row = m0 + wm + (mi << 4) + g;
            float o0 = (acc[mi][ni][0] + b0) * scale;
            float o1 = (acc[mi][ni][1] + b1) * scale;
            float o2 = (acc[mi][ni][2] + b0) * scale;
            float o3 = (acc[mi][ni][3] + b1) * scale;
            if (OUT_HALF) {
                __half* C = (__half*)Cout;
                *(__half2*)(C + (size_t)row * DD + col)       = __floats2half2_rn(o0, o1);
                *(__half2*)(C + (size_t)(row + 8) * DD + col) = __floats2half2_rn(o2, o3);
            } else {
                if (rnd_out) { o0 = rndtf(o0); o1 = rndtf(o1); o2 = rndtf(o2); o3 = rndtf(o3); }
                float* C = (float*)Cout;
                float* c0 = C + (size_t)row * DD + col;
                c0[0] = o0; c0[1] = o1;
                float* c2 = C + (size_t)(row + 8) * DD + col;
                c2[0] = o2; c2[1] = o3;
            }
        }
    }
}

// fused q/k/v projections: q,k -> fp16 (q scaled 1/8); v -> tf32-rounded fp32
__global__ __launch_bounds__(256, 3)
void projqkv_k(const float* __restrict__ query, const float* __restrict__ key,
               const float* __restrict__ value, const float* __restrict__ w_r,
               const float* __restrict__ bq, const float* __restrict__ bk,
               const float* __restrict__ bv,
               __half* __restrict__ qh, __half* __restrict__ kh,
               float* __restrict__ vo)
{
    extern __shared__ float smp[];
    int z = blockIdx.z;
    const float* A = (z == 0) ? query : (z == 1) ? key : value;
    const float* W = w_r + (size_t)z * DD * DD;
    const float* bi = (z == 0) ? bq : (z == 1) ? bk : bv;
    if (z == 0)      proj_body<1,1>(A, W, bi, qh, 0.125f, 0, smp, smp + 4608);
    else if (z == 1) proj_body<1,1>(A, W, bi, kh, 1.0f,   0, smp, smp + 4608);
    else             proj_body<1,0>(A, W, bi, vo, 1.0f,   1, smp, smp + 4608);
}

// output projection: A = o (already tf32), W pre-rounded
__global__ __launch_bounds__(256, 3)
void proj_o_k(const float* __restrict__ A, const float* __restrict__ W,
              const float* __restrict__ bias, float* __restrict__ C)
{
    extern __shared__ float smp[];
    proj_body<0,0>(A, W, bias, C, 1.0f, 0, smp, smp + 4608);
}

// ============================================================================
// Pass A (fp16 MMA): g_rz = 1 / sum_i exp(s),  s = K_j . Q_i (Q pre-scaled)
// block = (j-tile 128, bh) grid 384, 256 thr (2j x 4i warps, warp 64x32).
// K resident, Q i-tiles (128) single-buffered.
// smem: Kt half[128][72] + Qt half[128][72] + zp f32[512] = 38912 B, 2 CTA/SM.
// ============================================================================
__global__ __launch_bounds__(256, 2)
void stats_fused_k(const __half* __restrict__ Qp, const __half* __restrict__ Kp,
                   float* __restrict__ RZ)
{
    extern __shared__ char smc[];
    __half* Kt = (__half*)smc;              // [j][d] stride 72
    __half* Qt = (__half*)(smc + 18432);    // [i][d] stride 72
    float*  zp = (float*)(smc + 36864);     // [4][128]

    int bh = blockIdx.y;
    int b = bh / HH, h = bh % HH;
    int j0 = blockIdx.x << 7;

    int t = threadIdx.x, lane = t & 31, w = t >> 5;
    int g = lane >> 2, q = lane & 3;
    int wm = (w & 1) << 6, wn = (w >> 1) << 5;
    int wni = w >> 1;

    zp[t] = 0.f; zp[t + 256] = 0.f;

    // K tile resident: 128 rows x 64 halves = 8x16B chunks/row -> 4/thread
    #pragma unroll
    for (int ch = 0; ch < 4; ch++) {
        int c = t + (ch << 8);
        int row = c >> 3, cc = (c & 7) << 3;
        cpa16(&Kt[row * 72 + cc], Kp + (size_t)(b * SS + j0 + row) * DD + h * DKK + cc);
    }
    cp_commit();

    for (int it = 0; it < 16; it++) {
        #pragma unroll
        for (int ch = 0; ch < 4; ch++) {
            int c = t + (ch << 8);
            int row = c >> 3, cc = (c & 7) << 3;
            cpa16(&Qt[row * 72 + cc],
                  Qp + (size_t)(b * SS + (it << 7) + row) * DD + h * DKK + cc);
        }
        cp_commit();
        cp_wait<0>();
        __syncthreads();

        float acc[4][4][4] = {};
        #pragma unroll
        for (int kks = 0; kks < 4; kks++) {
            int kb = kks << 4;
            unsigned a[4][4], b2[4][2];
            #pragma unroll
            for (int mi = 0; mi < 4; mi++) {
                const __half* pa = &Kt[(wm + (mi << 4) + g) * 72 + kb + (q << 1)];
                a[mi][0] = *(const unsigned*)pa;
                a[mi][1] = *(const unsigned*)(pa + 8 * 72);
                a[mi][2] = *(const unsigned*)(pa + 8);
                a[mi][3] = *(const unsigned*)(pa + 8 * 72 + 8);
            }
            #pragma unroll
            for (int ni = 0; ni < 4; ni++) {
                const __half* pb = &Qt[(wn + (ni << 3) + g) * 72 + kb + (q << 1)];
                b2[ni][0] = *(const unsigned*)pb;
                b2[ni][1] = *(const unsigned*)(pb + 8);
            }
            #pragma unroll
            for (int mi = 0; mi < 4; mi++)
                #pragma unroll
                for (int ni = 0; ni < 4; ni++) mma16(acc[mi][ni], a[mi], b2[ni]);
        }

        #pragma unroll
        for (int mi = 0; mi < 4; mi++) {
            float s0 = 0.f, s1 = 0.f;
            #pragma unroll
            for (int ni = 0; ni < 4; ni++) {
                s0 += __expf(acc[mi][ni][0]) + __expf(acc[mi][ni][1]);
                s1 += __expf(acc[mi][ni][2]) + __expf(acc[mi][ni][3]);
            }
            s0 += __shfl_xor_sync(0xffffffffu, s0, 1);
            s0 += __shfl_xor_sync(0xffffffffu, s0, 2);
            s1 += __shfl_xor_sync(0xffffffffu, s1, 1);
            s1 += __shfl_xor_sync(0xffffffffu, s1, 2);
            if (q == 0) {
                zp[wni * 128 + wm + (mi << 4) + g]     += s0;
                zp[wni * 128 + wm + (mi << 4) + g + 8] += s1;
            }
        }
        __syncthreads();
    }

    if (t < 128) {
        float z = zp[t] + zp[128 + t] + zp[256 + t] + zp[384 + t];
        RZ[bh * SS + j0 + t] = 1.0f / z;
    }
}

// ============================================================================
// Pass B: O = sum_j exp(s)*rz[j] * V[j,d]
// MMA1 fp16 (K,Q half); exp -> Ps f32; MMA2 tf32 (Ps, V f32).
// block = (i-tile 128, bh), 256 thr, j-loop tile 64 (32 iters), 2 CTAs/SM.
// smem: Qt h[128][72](18432) + Kt h[64][72](9216) + Vt f[64][72](18432)
//       + Ps f[64][136](34816) = 80896 B
// ============================================================================
__global__ __launch_bounds__(256, 2)
void av_fused_k(const __half* __restrict__ Qp, const __half* __restrict__ Kp,
                const float* __restrict__ Vp, const float* __restrict__ RZ,
                float* __restrict__ O)
{
    extern __shared__ char smc[];
    __half* Qt = (__half*)smc;                 // [i][d] stride 72
    __half* Kt = (__half*)(smc + 18432);       // [j][d] stride 72
    float*  Vt = (float*)(smc + 18432 + 9216); // [j][d] stride 72
    float*  Ps = (float*)(smc + 18432 + 9216 + 18432);  // [j][i] stride 136

    int bh = blockIdx.y;
    int b = bh / HH, h = bh % HH;
    int i0 = blockIdx.x << 7;

    int t = threadIdx.x, lane = t & 31, w = t >> 5;
    int g = lane >> 2, q = lane & 3;
    int wj1 = (w & 1) << 5, wi1 = (w >> 1) << 5;   // MMA1: 2j x 4i (32x32)
    int wm2 = (w & 3) << 5, wn2 = (w >> 2) << 5;   // MMA2: 4i x 2d (32x32)

    // prologue: Q resident (half, 4 ch/thr) + K(0) (half, 2 ch/thr) group0; V(0) group1
    #pragma unroll
    for (int ch = 0; ch < 4; ch++) {
        int c = t + (ch << 8);
        int row = c >> 3, cc = (c & 7) << 3;
        cpa16(&Qt[row * 72 + cc], Qp + (size_t)(b * SS + i0 + row) * DD + h * DKK + cc);
    }
    #pragma unroll
    for (int ch = 0; ch < 2; ch++) {
        int c = t + (ch << 8);
        int row = c >> 3, cc = (c & 7) << 3;
        cpa16(&Kt[row * 72 + cc], Kp + (size_t)(b * SS + row) * DD + h * DKK + cc);
    }
    cp_commit();
    #pragma unroll
    for (int ch = 0; ch < 4; ch++) {
        int c = t + (ch << 8);
        int row = c >> 4, dq = (c & 15) << 2;
        cpa16(&Vt[row * 72 + dq], Vp + (size_t)(b * SS + row) * DD + h * DKK + dq);
    }
    cp_commit();

    float accO[2][4][4] = {};

    for (int it = 0; it < 32; it++) {
        int jc = it << 6;

        // prefetch RZ (hidden behind K-wait + MMA1)
        float rzv[2][2];
        #pragma unroll
        for (int mi = 0; mi < 2; mi++) {
            int r0 = wj1 + (mi << 4) + g;
            rzv[mi][0] = RZ[bh * SS + jc + r0];
            rzv[mi][1] = RZ[bh * SS + jc + r0 + 8];
        }

        cp_wait<1>();      // K(it) ready (V(it) may still be in flight)
        __syncthreads();

        // ---- MMA1 (fp16): S = K_tile(64j) @ Q_tile(128i)^T over d=64 ----
        float acc1[2][4][4] = {};
        #pragma unroll
        for (int kks = 0; kks < 4; kks++) {
            int kb = kks << 4;
            unsigned a[2][4], b2[4][2];
            #pragma unroll
            for (int mi = 0; mi < 2; mi++) {
                const __half* pa = &Kt[(wj1 + (mi << 4) + g) * 72 + kb + (q << 1)];
                a[mi][0] = *(const unsigned*)pa;
                a[mi][1] = *(const unsigned*)(pa + 8 * 72);
                a[mi][2] = *(const unsigned*)(pa + 8);
                a[mi][3] = *(const unsigned*)(pa + 8 * 72 + 8);
            }
            #pragma unroll
            for (int ni = 0; ni < 4; ni++) {
                const __half* pb = &Qt[(wi1 + (ni << 3) + g) * 72 + kb + (q << 1)];
                b2[ni][0] = *(const unsigned*)pb;
                b2[ni][1] = *(const unsigned*)(pb + 8);
            }
            #pragma unroll
            for (int mi = 0; mi < 2; mi++)
                #pragma unroll
                for (int ni = 0; ni < 4; ni++) mma16(acc1[mi][ni], a[mi], b2[ni]);
        }
        __syncthreads();   // Kt reads done

        if (it < 31) {     // prefetch K(it+1) (uncommitted yet)
            #pragma unroll
            for (int ch = 0; ch < 2; ch++) {
                int c = t + (ch << 8);
                int row = c >> 3, cc = (c & 7) << 3;
                cpa16(&Kt[row * 72 + cc],
                      Kp + (size_t)(b * SS + jc + 64 + row) * DD + h * DKK + cc);
            }
        }

        // ---- P = round_tf32( exp(s) * rz[j] ) -> Ps[j][i] (f32) ----
        #pragma unroll
        for (int mi = 0; mi < 2; mi++) {
            int r0 = wj1 + (mi << 4) + g;
            float rz0 = rzv[mi][0], rz1 = rzv[mi][1];
            #pragma unroll
            for (int ni = 0; ni < 4; ni++) {
                int col = wi1 + (ni << 3) + (q << 1);
                float2 p0 = make_float2(rndtf(__expf(acc1[mi][ni][0]) * rz0),
                                        rndtf(__expf(acc1[mi][ni][1]) * rz0));
                float2 p1 = make_float2(rndtf(__expf(acc1[mi][ni][2]) * rz1),
                                        rndtf(__expf(acc1[mi][ni][3]) * rz1));
                *(float2*)&Ps[r0 * 136 + col]       = p0;
                *(float2*)&Ps[(r0 + 8) * 136 + col] = p1;
            }
        }
        cp_wait<0>();      // V(it) ready (committed groups only)
        cp_commit();       // close K(it+1) group
        __syncthreads();   // Ps visible + Vt ready

        // ---- MMA2 (tf32): O += P^T(128i x 64j) @ V(64j x 64d) ----
        #pragma unroll
        for (int kk = 0; kk < 64; kk += 8) {
            unsigned a[2][4], b2[4][2];
            #pragma unroll
            for (int mi = 0; mi < 2; mi++) {
                const float* pa = &Ps[(kk + q) * 136 + wm2 + (mi << 4) + g];
                a[mi][0] = __float_as_uint(pa[0]);
                a[mi][1] = __float_as_uint(pa[8]);
                a[mi][2] = __float_as_uint(pa[4 * 136]);
                a[mi][3] = __float_as_uint(pa[4 * 136 + 8]);
            }
            #pragma unroll
            for (int ni = 0; ni < 4; ni++) {
                const float* pb = &Vt[(kk + q) * 72 + wn2 + (ni << 3) + g];
                b2[ni][0] = __float_as_uint(pb[0]);
                b2[ni][1] = __float_as_uint(pb[4 * 72]);
            }
            #pragma unroll
            for (int mi = 0; mi < 2; mi++)
                #pragma unroll
                for (int ni = 0; ni < 4; ni++) mma8(accO[mi][ni], a[mi], b2[ni]);
        }
        __syncthreads();   // Vt reads done

        if (it < 31) {     // prefetch V(it+1)
            #pragma unroll
            for (int ch = 0; ch < 4; ch++) {
                int c = t + (ch << 8);
                int row = c >> 4, dq = (c & 15) << 2;
                cpa16(&Vt[row * 72 + dq],
                      Vp + (size_t)(b * SS + jc + 64 + row) * DD + h * DKK + dq);
            }
            cp_commit();
        }
    }

    // epilogue: O rounded to tf32 (consumed by final projection)
    #pragma unroll
    for (int mi = 0; mi < 2; mi++) {
        #pragma unroll
        for (int ni = 0; ni < 4; ni++) {
            int row = i0 + wm2 + (mi << 4) + g;
            int col = h * DKK + wn2 + (ni << 3) + (q << 1);
            float2 o0 = make_float2(rndtf(accO[mi][ni][0]), rndtf(accO[mi][ni][1]));
            float2 o1 = make_float2(rndtf(accO[mi][ni][2]), rndtf(accO[mi][ni][3]));
            *(float2*)&O[(size_t)(b * SS + row) * DD + col]     = o0;
            *(float2*)&O[(size_t)(b * SS + row + 8) * DD + col] = o1;
        }
    }
}

// ---------------- launch -----------------------------------------------------
extern "C" void kernel_launch(void* const* d_in, const int* in_sizes, int n_in,
                              void* d_out, int out_size)
{
    const float* query = (const float*)d_in[0];
    const float* key   = (const float*)d_in[1];
    const float* value = (const float*)d_in[2];
    const float* Wq = (const float*)d_in[3];
    const float* bq = (const float*)d_in[4];
    const float* Wk = (const float*)d_in[5];
    const float* bk = (const float*)d_in[6];
    const float* Wv = (const float*)d_in[7];
    const float* bv = (const float*)d_in[8];
    const float* Wo = (const float*)d_in[9];
    const float* bo = (const float*)d_in[10];
    float* out = (float*)d_out;

    __half *qh, *kh;
    float *v, *o, *rz, *wr;
    cudaGetSymbolAddress((void**)&qh, g_qh);
    cudaGetSymbolAddress((void**)&kh, g_kh);
    cudaGetSymbolAddress((void**)&v,  g_v);
    cudaGetSymbolAddress((void**)&o,  g_o);
    cudaGetSymbolAddress((void**)&rz, g_rz);
    cudaGetSymbolAddress((void**)&wr, g_w);

    const int SMEM_P = (2 * 64 * 36 + 2 * 32 * 136) * 4;          // 53248
    const int SMEM_A = 18432 + 18432 + 2048;                      // 38912
    const int SMEM_B = 18432 + 9216 + 18432 + 34816;              // 80896
    cudaFuncSetAttribute(projqkv_k,     cudaFuncAttributeMaxDynamicSharedMemorySize, SMEM_P);
    cudaFuncSetAttribute(proj_o_k,      cudaFuncAttributeMaxDynamicSharedMemorySize, SMEM_P);
    cudaFuncSetAttribute(stats_fused_k, cudaFuncAttributeMaxDynamicSharedMemorySize, SMEM_A);
    cudaFuncSetAttribute(av_fused_k,    cudaFuncAttributeMaxDynamicSharedMemorySize, SMEM_B);

    // weights prepass (tiny): 4 x 768x768
    round_weights_k<<<dim3((DD * DD / 4 + 255) / 256, 4), 256>>>(Wq, Wk, Wv, Wo, wr);

    // fused q/k/v projections: grid (6, 64, 3)
    projqkv_k<<<dim3(DD / 128, MM / 64, 3), 256, SMEM_P>>>(query, key, value, wr,
                                                           bq, bk, bv, qh, kh, v);

    stats_fused_k<<<dim3(SS / 128, BB * HH), 256, SMEM_A>>>(qh, kh, rz);

    av_fused_k<<<dim3(SS / 128, BB * HH), 256, SMEM_B>>>(qh, kh, v, rz, o);

    proj_o_k<<<dim3(DD / 128, MM / 64), 256, SMEM_P>>>(o, wr + (size_t)3 * DD * DD, bo, out);
}

// round 15
// speedup vs baseline: 1.3974x; 1.1371x over previous
#include <cuda_runtime.h>
#include <cuda_fp16.h>

#define BB 2
#define SS 2048
#define DD 768
#define HH 12
#define DKK 64
#define MM (BB*SS)   // 4096

// ---------------- scratch (static device globals) ---------------------------
__device__ __half g_qh[MM * DD];       // fp16 q (pre-scaled 1/8)
__device__ __half g_kh[MM * DD];       // fp16 k
__device__ __half g_vh[MM * DD];       // fp16 v
__device__ float  g_o [MM * DD];       // tf32-rounded attention output
__device__ float  g_rz[BB * HH * SS];  // 1 / sum_i exp(s[b,h,j,i])
__device__ float  g_w [4 * DD * DD];   // tf32-rounded Wq/Wk/Wv/Wo

// ---------------- helpers ----------------------------------------------------
__device__ __forceinline__ void cpa16(void* s, const void* g) {
    unsigned sa = (unsigned)__cvta_generic_to_shared(s);
    asm volatile("cp.async.ca.shared.global [%0], [%1], 16;\n" :: "r"(sa), "l"(g));
}
__device__ __forceinline__ void cp_commit() { asm volatile("cp.async.commit_group;\n"); }
template<int N> __device__ __forceinline__ void cp_wait() {
    asm volatile("cp.async.wait_group %0;\n" :: "n"(N));
}
__device__ __forceinline__ unsigned f2tf(float f) {
    unsigned u;
    asm("cvt.rna.tf32.f32 %0, %1;" : "=r"(u) : "f"(f));
    return u;
}
__device__ __forceinline__ float rndtf(float f) { return __uint_as_float(f2tf(f)); }

// tf32: D += A(16x8) * B(8x8)
__device__ __forceinline__ void mma8(float c[4], const unsigned a[4], const unsigned b[2]) {
    asm volatile(
        "mma.sync.aligned.m16n8k8.row.col.f32.tf32.tf32.f32 "
        "{%0,%1,%2,%3}, {%4,%5,%6,%7}, {%8,%9}, {%0,%1,%2,%3};"
        : "+f"(c[0]), "+f"(c[1]), "+f"(c[2]), "+f"(c[3])
        : "r"(a[0]), "r"(a[1]), "r"(a[2]), "r"(a[3]), "r"(b[0]), "r"(b[1]));
}
// fp16: D += A(16x16) * B(16x8), f32 accum
__device__ __forceinline__ void mma16(float c[4], const unsigned a[4], const unsigned b[2]) {
    asm volatile(
        "mma.sync.aligned.m16n8k16.row.col.f32.f16.f16.f32 "
        "{%0,%1,%2,%3}, {%4,%5,%6,%7}, {%8,%9}, {%0,%1,%2,%3};"
        : "+f"(c[0]), "+f"(c[1]), "+f"(c[2]), "+f"(c[3])
        : "r"(a[0]), "r"(a[1]), "r"(a[2]), "r"(a[3]), "r"(b[0]), "r"(b[1]));
}
// ldmatrix x4 transposed b16
__device__ __forceinline__ void ldsm4t(unsigned r[4], unsigned addr) {
    asm volatile("ldmatrix.sync.aligned.m8n8.x4.trans.shared.b16 {%0,%1,%2,%3}, [%4];"
        : "=r"(r[0]), "=r"(r[1]), "=r"(r[2]), "=r"(r[3]) : "r"(addr));
}

// ============================================================================
// Weights tf32 pre-rounding
// ============================================================================
__global__ void round_weights_k(const float* __restrict__ wq,
                                const float* __restrict__ wk,
                                const float* __restrict__ wv,
                                const float* __restrict__ wo,
                                float* __restrict__ dst)
{
    const float* src = (blockIdx.y == 0) ? wq : (blockIdx.y == 1) ? wk
                     : (blockIdx.y == 2) ? wv : wo;
    float* d = dst + (size_t)blockIdx.y * DD * DD;
    int idx = (blockIdx.x * 256 + threadIdx.x) << 2;
    if (idx < DD * DD) {
        float4 x = *(const float4*)(src + idx);
        x.x = rndtf(x.x); x.y = rndtf(x.y); x.z = rndtf(x.z); x.w = rndtf(x.w);
        *(float4*)(d + idx) = x;
    }
}

// ============================================================================
// Projection GEMM body: out = ((A @ W) + bias) * scale
// 64m x 128n tile, BK=32 (24 iters), 256 thr (2x4 warps, warp 32x32).
// ============================================================================
#define PAS(buf,m,k)  As[(buf)*2304 + (m)*36 + (k)]
#define PBS(buf,k,n)  Bs[(buf)*4352 + (k)*136 + (n)]

template<int RND_A, int OUT_HALF>
__device__ __forceinline__
void proj_body(const float* __restrict__ A, const float* __restrict__ W,
               const float* __restrict__ bias, void* __restrict__ Cout,
               float scale, int rnd_out, float* As, float* Bs)
{
    int t = threadIdx.x, lane = t & 31, w = t >> 5;
    int g = lane >> 2, q = lane & 3;
    int wm = (w & 1) << 5, wn = (w >> 1) << 5;
    int m0 = blockIdx.y << 6, n0 = blockIdx.x << 7;

    {
        #pragma unroll
        for (int ch = 0; ch < 2; ch++) {
            int c = t + (ch << 8);
            int ar = c >> 3, akq = (c & 7) << 2;
            cpa16(&PAS(0, ar, akq), A + (size_t)(m0 + ar) * DD + akq);
        }
        #pragma unroll
        for (int ch = 0; ch < 4; ch++) {
            int c = t + (ch << 8);
            int br = c >> 5, bnq = (c & 31) << 2;
            cpa16(&PBS(0, br, bnq), W + (size_t)br * DD + n0 + bnq);
        }
    }
    cp_commit();

    float acc[2][4][4] = {};

    for (int it = 0; it < 24; it++) {
        int buf = it & 1;
        if (it < 23) {
            int k0 = (it + 1) << 5;
            #pragma unroll
            for (int ch = 0; ch < 2; ch++) {
                int c = t + (ch << 8);
                int ar = c >> 3, akq = (c & 7) << 2;
                cpa16(&PAS(buf ^ 1, ar, akq), A + (size_t)(m0 + ar) * DD + k0 + akq);
            }
            #pragma unroll
            for (int ch = 0; ch < 4; ch++) {
                int c = t + (ch << 8);
                int br = c >> 5, bnq = (c & 31) << 2;
                cpa16(&PBS(buf ^ 1, br, bnq), W + (size_t)(k0 + br) * DD + n0 + bnq);
            }
            cp_commit();
            cp_wait<1>();
        } else {
            cp_wait<0>();
        }
        __syncthreads();

        #pragma unroll
        for (int kk = 0; kk < 32; kk += 8) {
            unsigned a[2][4], b2[4][2];
            #pragma unroll
            for (int mi = 0; mi < 2; mi++) {
                const float* pa = &PAS(buf, wm + (mi << 4) + g, kk + q);
                if (RND_A) {
                    a[mi][0] = f2tf(pa[0]);
                    a[mi][1] = f2tf(pa[8 * 36]);
                    a[mi][2] = f2tf(pa[4]);
                    a[mi][3] = f2tf(pa[8 * 36 + 4]);
                } else {
                    a[mi][0] = __float_as_uint(pa[0]);
                    a[mi][1] = __float_as_uint(pa[8 * 36]);
                    a[mi][2] = __float_as_uint(pa[4]);
                    a[mi][3] = __float_as_uint(pa[8 * 36 + 4]);
                }
            }
            #pragma unroll
            for (int ni = 0; ni < 4; ni++) {
                const float* pb = &PBS(buf, kk + q, wn + (ni << 3) + g);
                b2[ni][0] = __float_as_uint(pb[0]);
                b2[ni][1] = __float_as_uint(pb[4 * 136]);
            }
            #pragma unroll
            for (int mi = 0; mi < 2; mi++)
                #pragma unroll
                for (int ni = 0; ni < 4; ni++) mma8(acc[mi][ni], a[mi], b2[ni]);
        }
        __syncthreads();
    }

    #pragma unroll
    for (int ni = 0; ni < 4; ni++) {
        int col = n0 + wn + (ni << 3) + (q << 1);
        float b0 = bias[col], b1 = bias[col + 1];
        #pragma unroll
        for (int mi = 0; mi < 2; mi++) {
            int row = m0 + wm + (mi << 4) + g;
            float o0 = (acc[mi][ni][0] + b0) * scale;
            float o1 = (acc[mi][ni][1] + b1) * scale;
            float o2 = (acc[mi][ni][2] + b0) * scale;
            float o3 = (acc[mi][ni][3] + b1) * scale;
            if (OUT_HALF) {
                __half* C = (__half*)Cout;
                *(__half2*)(C + (size_t)row * DD + col)       = __floats2half2_rn(o0, o1);
                *(__half2*)(C + (size_t)(row + 8) * DD + col) = __floats2half2_rn(o2, o3);
            } else {
                if (rnd_out) { o0 = rndtf(o0); o1 = rndtf(o1); o2 = rndtf(o2); o3 = rndtf(o3); }
                float* C = (float*)Cout;
                float* c0 = C + (size_t)row * DD + col;
                c0[0] = o0; c0[1] = o1;
                float* c2 = C + (size_t)(row + 8) * DD + col;
                c2[0] = o2; c2[1] = o3;
            }
        }
    }
}

// fused q/k/v projections -> all fp16 (q scaled 1/8)
__global__ __launch_bounds__(256, 3)
void projqkv_k(const float* __restrict__ query, const float* __restrict__ key,
               const float* __restrict__ value, const float* __restrict__ w_r,
               const float* __restrict__ bq, const float* __restrict__ bk,
               const float* __restrict__ bv,
               __half* __restrict__ qh, __half* __restrict__ kh,
               __half* __restrict__ vh)
{
    extern __shared__ float smp[];
    int z = blockIdx.z;
    const float* A = (z == 0) ? query : (z == 1) ? key : value;
    const float* W = w_r + (size_t)z * DD * DD;
    const float* bi = (z == 0) ? bq : (z == 1) ? bk : bv;
    __half* C = (z == 0) ? qh : (z == 1) ? kh : vh;
    float scale = (z == 0) ? 0.125f : 1.0f;
    proj_body<1,1>(A, W, bi, C, scale, 0, smp, smp + 4608);
}

// output projection: A = o (already tf32), W pre-rounded
__global__ __launch_bounds__(256, 3)
void proj_o_k(const float* __restrict__ A, const float* __restrict__ W,
              const float* __restrict__ bias, float* __restrict__ C)
{
    extern __shared__ float smp[];
    proj_body<0,0>(A, W, bias, C, 1.0f, 0, smp, smp + 4608);
}

// ============================================================================
// Pass A (fp16 MMA, R14 config): g_rz = 1 / sum_i exp(s)
// block = (j-tile 128, bh) grid 384, 256 thr (2j x 4i warps, warp 64x32).
// smem: Kt h[128][72] + Qt h[128][72] + zp f32[512] = 38912 B, 2 CTA/SM.
// ============================================================================
__global__ __launch_bounds__(256, 2)
void stats_fused_k(const __half* __restrict__ Qp, const __half* __restrict__ Kp,
                   float* __restrict__ RZ)
{
    extern __shared__ char smc[];
    __half* Kt = (__half*)smc;              // [j][d] stride 72
    __half* Qt = (__half*)(smc + 18432);    // [i][d] stride 72
    float*  zp = (float*)(smc + 36864);     // [4][128]

    int bh = blockIdx.y;
    int b = bh / HH, h = bh % HH;
    int j0 = blockIdx.x << 7;

    int t = threadIdx.x, lane = t & 31, w = t >> 5;
    int g = lane >> 2, q = lane & 3;
    int wm = (w & 1) << 6, wn = (w >> 1) << 5;
    int wni = w >> 1;

    zp[t] = 0.f; zp[t + 256] = 0.f;

    #pragma unroll
    for (int ch = 0; ch < 4; ch++) {
        int c = t + (ch << 8);
        int row = c >> 3, cc = (c & 7) << 3;
        cpa16(&Kt[row * 72 + cc], Kp + (size_t)(b * SS + j0 + row) * DD + h * DKK + cc);
    }
    cp_commit();

    for (int it = 0; it < 16; it++) {
        #pragma unroll
        for (int ch = 0; ch < 4; ch++) {
            int c = t + (ch << 8);
            int row = c >> 3, cc = (c & 7) << 3;
            cpa16(&Qt[row * 72 + cc],
                  Qp + (size_t)(b * SS + (it << 7) + row) * DD + h * DKK + cc);
        }
        cp_commit();
        cp_wait<0>();
        __syncthreads();

        float acc[4][4][4] = {};
        #pragma unroll
        for (int kks = 0; kks < 4; kks++) {
            int kb = kks << 4;
            unsigned a[4][4], b2[4][2];
            #pragma unroll
            for (int mi = 0; mi < 4; mi++) {
                const __half* pa = &Kt[(wm + (mi << 4) + g) * 72 + kb + (q << 1)];
                a[mi][0] = *(const unsigned*)pa;
                a[mi][1] = *(const unsigned*)(pa + 8 * 72);
                a[mi][2] = *(const unsigned*)(pa + 8);
                a[mi][3] = *(const unsigned*)(pa + 8 * 72 + 8);
            }
            #pragma unroll
            for (int ni = 0; ni < 4; ni++) {
                const __half* pb = &Qt[(wn + (ni << 3) + g) * 72 + kb + (q << 1)];
                b2[ni][0] = *(const unsigned*)pb;
                b2[ni][1] = *(const unsigned*)(pb + 8);
            }
            #pragma unroll
            for (int mi = 0; mi < 4; mi++)
                #pragma unroll
                for (int ni = 0; ni < 4; ni++) mma16(acc[mi][ni], a[mi], b2[ni]);
        }

        #pragma unroll
        for (int mi = 0; mi < 4; mi++) {
            float s0 = 0.f, s1 = 0.f;
            #pragma unroll
            for (int ni = 0; ni < 4; ni++) {
                s0 += __expf(acc[mi][ni][0]) + __expf(acc[mi][ni][1]);
                s1 += __expf(acc[mi][ni][2]) + __expf(acc[mi][ni][3]);
            }
            s0 += __shfl_xor_sync(0xffffffffu, s0, 1);
            s0 += __shfl_xor_sync(0xffffffffu, s0, 2);
            s1 += __shfl_xor_sync(0xffffffffu, s1, 1);
            s1 += __shfl_xor_sync(0xffffffffu, s1, 2);
            if (q == 0) {
                zp[wni * 128 + wm + (mi << 4) + g]     += s0;
                zp[wni * 128 + wm + (mi << 4) + g + 8] += s1;
            }
        }
        __syncthreads();
    }

    if (t < 128) {
        float z = zp[t] + zp[128 + t] + zp[256 + t] + zp[384 + t];
        RZ[bh * SS + j0 + t] = 1.0f / z;
    }
}

// ============================================================================
// Pass B: O = sum_j exp(s)*rz[j] * V[j,d] — ALL fp16 MMA.
// MMA1 fp16 (K,Q); P -> half2 Ps[j][i]; MMA2 fp16 via ldmatrix.x4.trans
// (A = P^T from Ps, B = V^T from Vt).
// block = (i-tile 128, bh), 256 thr, j-tile 64 (32 iters), 2 CTAs/SM.
// smem: Qt h[128][72](18432) + Kt h[64][72](9216) + Vt h[64][72](9216)
//       + Ps h[64][136](17408) = 54272 B
// ============================================================================
__global__ __launch_bounds__(256, 2)
void av_fused_k(const __half* __restrict__ Qp, const __half* __restrict__ Kp,
                const __half* __restrict__ Vp, const float* __restrict__ RZ,
                float* __restrict__ O)
{
    extern __shared__ char smc[];
    __half* Qt = (__half*)smc;                        // [i][d] stride 72
    __half* Kt = (__half*)(smc + 18432);              // [j][d] stride 72
    __half* Vt = (__half*)(smc + 18432 + 9216);       // [j][d] stride 72
    __half* Ps = (__half*)(smc + 18432 + 2 * 9216);   // [j][i] stride 136

    unsigned ps_u32 = (unsigned)__cvta_generic_to_shared(Ps);
    unsigned vt_u32 = (unsigned)__cvta_generic_to_shared(Vt);

    int bh = blockIdx.y;
    int b = bh / HH, h = bh % HH;
    int i0 = blockIdx.x << 7;

    int t = threadIdx.x, lane = t & 31, w = t >> 5;
    int g = lane >> 2, q = lane & 3;
    int lr = lane & 7;
    int wj1 = (w & 1) << 5, wi1 = (w >> 1) << 5;   // MMA1: 2j x 4i (32x32)
    int wm2 = (w & 3) << 5, wn2 = (w >> 2) << 5;   // MMA2: 4i x 2d (32x32)

    // ldmatrix lane address components (constant per thread)
    int kA_off = lr + ((lane >> 4) << 3);          // A: k = kb + this
    int iA_off = wm2 + (lane & 8);                 // A: i = this + mi*16
    int kB_off = lr + (lane & 8);                  // B: k = kb + this
    int dB_off = wn2 + ((lane >> 4) << 3);         // B: d = this + nb*16

    // prologue: Q resident + K(0) group0; V(0) group1 (all half)
    #pragma unroll
    for (int ch = 0; ch < 4; ch++) {
        int c = t + (ch << 8);
        int row = c >> 3, cc = (c & 7) << 3;
        cpa16(&Qt[row * 72 + cc], Qp + (size_t)(b * SS + i0 + row) * DD + h * DKK + cc);
    }
    #pragma unroll
    for (int ch = 0; ch < 2; ch++) {
        int c = t + (ch << 8);
        int row = c >> 3, cc = (c & 7) << 3;
        cpa16(&Kt[row * 72 + cc], Kp + (size_t)(b * SS + row) * DD + h * DKK + cc);
    }
    cp_commit();
    #pragma unroll
    for (int ch = 0; ch < 2; ch++) {
        int c = t + (ch << 8);
        int row = c >> 3, cc = (c & 7) << 3;
        cpa16(&Vt[row * 72 + cc], Vp + (size_t)(b * SS + row) * DD + h * DKK + cc);
    }
    cp_commit();

    float accO[2][4][4] = {};

    for (int it = 0; it < 32; it++) {
        int jc = it << 6;

        // prefetch RZ (hidden behind K-wait + MMA1)
        float rzv[2][2];
        #pragma unroll
        for (int mi = 0; mi < 2; mi++) {
            int r0 = wj1 + (mi << 4) + g;
            rzv[mi][0] = RZ[bh * SS + jc + r0];
            rzv[mi][1] = RZ[bh * SS + jc + r0 + 8];
        }

        cp_wait<1>();      // K(it) ready
        __syncthreads();

        // ---- MMA1 (fp16): S = K_tile(64j) @ Q_tile(128i)^T over d=64 ----
        float acc1[2][4][4] = {};
        #pragma unroll
        for (int kks = 0; kks < 4; kks++) {
            int kb = kks << 4;
            unsigned a[2][4], b2[4][2];
            #pragma unroll
            for (int mi = 0; mi < 2; mi++) {
                const __half* pa = &Kt[(wj1 + (mi << 4) + g) * 72 + kb + (q << 1)];
                a[mi][0] = *(const unsigned*)pa;
                a[mi][1] = *(const unsigned*)(pa + 8 * 72);
                a[mi][2] = *(const unsigned*)(pa + 8);
                a[mi][3] = *(const unsigned*)(pa + 8 * 72 + 8);
            }
            #pragma unroll
            for (int ni = 0; ni < 4; ni++) {
                const __half* pb = &Qt[(wi1 + (ni << 3) + g) * 72 + kb + (q << 1)];
                b2[ni][0] = *(const unsigned*)pb;
                b2[ni][1] = *(const unsigned*)(pb + 8);
            }
            #pragma unroll
            for (int mi = 0; mi < 2; mi++)
                #pragma unroll
                for (int ni = 0; ni < 4; ni++) mma16(acc1[mi][ni], a[mi], b2[ni]);
        }
        __syncthreads();   // Kt reads done

        if (it < 31) {     // prefetch K(it+1) (uncommitted)
            #pragma unroll
            for (int ch = 0; ch < 2; ch++) {
                int c = t + (ch << 8);
                int row = c >> 3, cc = (c & 7) << 3;
                cpa16(&Kt[row * 72 + cc],
                      Kp + (size_t)(b * SS + jc + 64 + row) * DD + h * DKK + cc);
            }
        }

        // ---- P = half( exp(s) * rz[j] ) -> Ps[j][i] ----
        #pragma unroll
        for (int mi = 0; mi < 2; mi++) {
            int r0 = wj1 + (mi << 4) + g;
            float rz0 = rzv[mi][0], rz1 = rzv[mi][1];
            #pragma unroll
            for (int ni = 0; ni < 4; ni++) {
                int col = wi1 + (ni << 3) + (q << 1);
                *(__half2*)&Ps[r0 * 136 + col] =
                    __floats2half2_rn(__expf(acc1[mi][ni][0]) * rz0,
                                      __expf(acc1[mi][ni][1]) * rz0);
                *(__half2*)&Ps[(r0 + 8) * 136 + col] =
                    __floats2half2_rn(__expf(acc1[mi][ni][2]) * rz1,
                                      __expf(acc1[mi][ni][3]) * rz1);
            }
        }
        cp_wait<0>();      // V(it) ready
        cp_commit();       // close K(it+1) group
        __syncthreads();   // Ps visible + Vt ready

        // ---- MMA2 (fp16): O += P^T(128i x 64j) @ V(64j x 64d) ----
        #pragma unroll
        for (int kks = 0; kks < 4; kks++) {
            int kb = kks << 4;
            unsigned a4[2][4], b4[2][4];
            #pragma unroll
            for (int mi = 0; mi < 2; mi++)
                ldsm4t(a4[mi], ps_u32 +
                       (unsigned)(((kb + kA_off) * 136 + iA_off + (mi << 4)) << 1));
            #pragma unroll
            for (int nb = 0; nb < 2; nb++)
                ldsm4t(b4[nb], vt_u32 +
                       (unsigned)(((kb + kB_off) * 72 + dB_off + (nb << 4)) << 1));
            #pragma unroll
            for (int mi = 0; mi < 2; mi++) {
                mma16(accO[mi][0], a4[mi], &b4[0][0]);
                mma16(accO[mi][1], a4[mi], &b4[0][2]);
                mma16(accO[mi][2], a4[mi], &b4[1][0]);
                mma16(accO[mi][3], a4[mi], &b4[1][2]);
            }
        }
        __syncthreads();   // Vt + Ps reads done

        if (it < 31) {     // prefetch V(it+1)
            #pragma unroll
            for (int ch = 0; ch < 2; ch++) {
                int c = t + (ch << 8);
                int row = c >> 3, cc = (c & 7) << 3;
                cpa16(&Vt[row * 72 + cc],
                      Vp + (size_t)(b * SS + jc + 64 + row) * DD + h * DKK + cc);
            }
            cp_commit();
        }
    }

    // epilogue: O rounded to tf32 (consumed by final projection)
    #pragma unroll
    for (int mi = 0; mi < 2; mi++) {
        #pragma unroll
        for (int ni = 0; ni < 4; ni++) {
            int row = i0 + wm2 + (mi << 4) + g;
            int col = h * DKK + wn2 + (ni << 3) + (q << 1);
            float2 o0 = make_float2(rndtf(accO[mi][ni][0]), rndtf(accO[mi][ni][1]));
            float2 o1 = make_float2(rndtf(accO[mi][ni][2]), rndtf(accO[mi][ni][3]));
            *(float2*)&O[(size_t)(b * SS + row) * DD + col]     = o0;
            *(float2*)&O[(size_t)(b * SS + row + 8) * DD + col] = o1;
        }
    }
}

// ---------------- launch -----------------------------------------------------
extern "C" void kernel_launch(void* const* d_in, const int* in_sizes, int n_in,
                              void* d_out, int out_size)
{
    const float* query = (const float*)d_in[0];
    const float* key   = (const float*)d_in[1];
    const float* value = (const float*)d_in[2];
    const float* Wq = (const float*)d_in[3];
    const float* bq = (const float*)d_in[4];
    const float* Wk = (const float*)d_in[5];
    const float* bk = (const float*)d_in[6];
    const float* Wv = (const float*)d_in[7];
    const float* bv = (const float*)d_in[8];
    const float* Wo = (const float*)d_in[9];
    const float* bo = (const float*)d_in[10];
    float* out = (float*)d_out;

    __half *qh, *kh, *vh;
    float *o, *rz, *wr;
    cudaGetSymbolAddress((void**)&qh, g_qh);
    cudaGetSymbolAddress((void**)&kh, g_kh);
    cudaGetSymbolAddress((void**)&vh, g_vh);
    cudaGetSymbolAddress((void**)&o,  g_o);
    cudaGetSymbolAddress((void**)&rz, g_rz);
    cudaGetSymbolAddress((void**)&wr, g_w);

    const int SMEM_P = (2 * 64 * 36 + 2 * 32 * 136) * 4;          // 53248
    const int SMEM_A = 18432 + 18432 + 2048;                      // 38912
    const int SMEM_B = 18432 + 9216 + 9216 + 17408;               // 54272
    cudaFuncSetAttribute(projqkv_k,     cudaFuncAttributeMaxDynamicSharedMemorySize, SMEM_P);
    cudaFuncSetAttribute(proj_o_k,      cudaFuncAttributeMaxDynamicSharedMemorySize, SMEM_P);
    cudaFuncSetAttribute(stats_fused_k, cudaFuncAttributeMaxDynamicSharedMemorySize, SMEM_A);
    cudaFuncSetAttribute(av_fused_k,    cudaFuncAttributeMaxDynamicSharedMemorySize, SMEM_B);

    round_weights_k<<<dim3((DD * DD / 4 + 255) / 256, 4), 256>>>(Wq, Wk, Wv, Wo, wr);

    projqkv_k<<<dim3(DD / 128, MM / 64, 3), 256, SMEM_P>>>(query, key, value, wr,
                                                           bq, bk, bv, qh, kh, vh);

    stats_fused_k<<<dim3(SS / 128, BB * HH), 256, SMEM_A>>>(qh, kh, rz);

    av_fused_k<<<dim3(SS / 128, BB * HH), 256, SMEM_B>>>(qh, kh, vh, rz, o);

    proj_o_k<<<dim3(DD / 128, MM / 64), 256, SMEM_P>>>(o, wr + (size_t)3 * DD * DD, bo, out);
}